// round 16
// baseline (speedup 1.0000x reference)
#include <cuda_runtime.h>

#define BATCH 4096
#define NCLS  10000
#define DIM   256
#define ALPHA 0.5f
#define CAP   64   // per-class row-list capacity (overflow handled exactly)

// Scratch (allocation-free: __device__ globals).
// g_cnt starts zeroed (static init); K2 re-zeroes ONLY touched classes
// (untouched are already 0) -> no zero kernel.
__device__ int g_cnt[NCLS];         // per-class sample count
__device__ int g_label[BATCH];      // decoded label per row (overflow fallback)
__device__ int g_rows[NCLS * CAP];  // per-class row index list (8B aligned rows)

// ---------------------------------------------------------------------------
// K1: ONE WARP PER ROW, depth-1 software pipeline (round-12 version: lowest
// register pressure, zero barriers, zero cross-warp coordination).
// 4096 warps = 512 blocks of 8 warps. Each iteration covers 2 KB (4
// float4/lane); next iteration's loads issue before testing the current
// buffer (ballot early-exit, warp-internal).
// ---------------------------------------------------------------------------
__global__ __launch_bounds__(256, 4)
void scan_loss_kernel(const float* __restrict__ onehot,
                      const float* __restrict__ feat,
                      const float* __restrict__ centers,
                      float* __restrict__ loss_out) {
    const int lane = threadIdx.x & 31;
    const int b    = blockIdx.x * 8 + (threadIdx.x >> 5);  // row for this warp

    const float4* row = reinterpret_cast<const float4*>(onehot + (size_t)b * NCLS);
    const int NV4 = NCLS / 4;            // 2500 float4
    const int PER_IT = 128;              // float4 per iteration (32 lanes x 4)
    const int NIT = (NV4 + PER_IT - 1) / PER_IT;  // 20

    float4 buf[4];
    #pragma unroll
    for (int k = 0; k < 4; ++k) {
        int i = lane + 32 * k;
        buf[k] = (i < NV4) ? row[i] : make_float4(0.f, 0.f, 0.f, 0.f);
    }

    int label = -1;
    #pragma unroll 1
    for (int it = 0; it < NIT; ++it) {
        // issue next iteration's loads BEFORE testing the current buffer
        float4 nxt[4];
        if (it + 1 < NIT) {
            #pragma unroll
            for (int k = 0; k < 4; ++k) {
                int i = (it + 1) * PER_IT + lane + 32 * k;
                nxt[k] = (i < NV4) ? row[i] : make_float4(0.f, 0.f, 0.f, 0.f);
            }
        }
        int found = -1;
        const int base = it * PER_IT;
        #pragma unroll
        for (int k = 0; k < 4; ++k) {
            int i = base + lane + 32 * k;
            if (buf[k].x != 0.f)      found = 4 * i + 0;
            else if (buf[k].y != 0.f) found = 4 * i + 1;
            else if (buf[k].z != 0.f) found = 4 * i + 2;
            else if (buf[k].w != 0.f) found = 4 * i + 3;
        }
        unsigned m = __ballot_sync(0xFFFFFFFFu, found >= 0);
        if (m) {
            const int src = __ffs(m) - 1;          // exactly one lane finds it
            if (lane == src) {
                g_label[b] = found;
                int slot = atomicAdd(&g_cnt[found], 1);
                if (slot < CAP) g_rows[found * CAP + slot] = b;
            }
            label = __shfl_sync(0xFFFFFFFFu, found, src);
            break;
        }
        #pragma unroll
        for (int k = 0; k < 4; ++k) buf[k] = nxt[k];
    }

    // loss vs OLD centers: lane owns dims [lane*8, lane*8+8)
    const float4* frow = reinterpret_cast<const float4*>(feat + (size_t)b * DIM);
    const float4* crow = reinterpret_cast<const float4*>(centers + (size_t)label * DIM);
    float4 fA = frow[lane * 2], fB = frow[lane * 2 + 1];
    float4 cA = crow[lane * 2], cB = crow[lane * 2 + 1];
    float dx, sq;
    dx = fA.x - cA.x; sq  = dx * dx;
    dx = fA.y - cA.y; sq += dx * dx;
    dx = fA.z - cA.z; sq += dx * dx;
    dx = fA.w - cA.w; sq += dx * dx;
    dx = fB.x - cB.x; sq += dx * dx;
    dx = fB.y - cB.y; sq += dx * dx;
    dx = fB.z - cB.z; sq += dx * dx;
    dx = fB.w - cB.w; sq += dx * dx;
    #pragma unroll
    for (int off = 16; off > 0; off >>= 1)
        sq += __shfl_down_sync(0xFFFFFFFFu, sq, off);
    if (lane == 0) loss_out[b] = sq;
}

// ---------------------------------------------------------------------------
// K2': SPARSE center update. out_centers already holds a verbatim copy of
// centers (DMA memcpy issued before this kernel in the same stream). One
// warp per class; 66% of warps (n==0) load one broadcast counter word and
// EXIT — no centers read, no store, no counter store (already zero).
// Touched classes (n>=1) overwrite their full row:
//   out_c = k*centers_c + s*sum(feat rows)   k=1-a*n/(n+1), s=a/(n+1)
// lane 0 cleans the counter after the warp-wide load (warp program order ->
// race-free, no barriers).
// ---------------------------------------------------------------------------
__global__ __launch_bounds__(256)
void sparse_update_kernel(const float* __restrict__ centers,
                          const float* __restrict__ feat,
                          float* __restrict__ out_centers) {
    const int c    = (blockIdx.x * blockDim.x + threadIdx.x) >> 5;  // class; grid exact
    const int lane = threadIdx.x & 31;

    const int n = g_cnt[c];                 // broadcast LDG (1 sector/warp)
    if (n == 0) return;                     // 66% of classes: memcpy already wrote it

    if (lane == 0) g_cnt[c] = 0;            // warp program order: race-free

    const int2 r01 = *reinterpret_cast<const int2*>(&g_rows[c * CAP]);
    const float4* crow = reinterpret_cast<const float4*>(centers) + (size_t)c * 64;
    float4 a0 = crow[lane];
    float4 a1 = crow[lane + 32];

    const float fn = (float)n;
    const float s = __fdividef(ALPHA, fn + 1.0f);
    const float k = 1.0f - fn * s;
    a0.x *= k; a0.y *= k; a0.z *= k; a0.w *= k;
    a1.x *= k; a1.y *= k; a1.z *= k; a1.w *= k;

    const float4* feat4 = reinterpret_cast<const float4*>(feat);

    // n<=2 covers 99.4% of touched classes; up to 4 independent gathers
    float4 f00 = feat4[(size_t)r01.x * 64 + lane];
    float4 f01 = feat4[(size_t)r01.x * 64 + lane + 32];
    float4 f10 = make_float4(0.f, 0.f, 0.f, 0.f);
    float4 f11 = make_float4(0.f, 0.f, 0.f, 0.f);
    if (n >= 2) {
        f10 = feat4[(size_t)r01.y * 64 + lane];
        f11 = feat4[(size_t)r01.y * 64 + lane + 32];
    }
    a0.x += s * (f00.x + f10.x); a0.y += s * (f00.y + f10.y);
    a0.z += s * (f00.z + f10.z); a0.w += s * (f00.w + f10.w);
    a1.x += s * (f01.x + f11.x); a1.y += s * (f01.y + f11.y);
    a1.z += s * (f01.z + f11.z); a1.w += s * (f01.w + f11.w);

    if (n > 2) {
        const int m = (n <= CAP) ? n : CAP;
        #pragma unroll 1
        for (int j = 2; j < m; ++j) {
            int bj = g_rows[c * CAP + j];
            float4 g0 = feat4[(size_t)bj * 64 + lane];
            float4 g1 = feat4[(size_t)bj * 64 + lane + 32];
            a0.x += s * g0.x; a0.y += s * g0.y; a0.z += s * g0.z; a0.w += s * g0.w;
            a1.x += s * g1.x; a1.y += s * g1.y; a1.z += s * g1.z; a1.w += s * g1.w;
        }
        if (n > CAP) {
            // exhaustive fallback (statistically unreachable; exact)
            #pragma unroll 1
            for (int bb = 0; bb < BATCH; ++bb) {
                if (g_label[bb] == c) {
                    bool seen = false;
                    for (int j = 0; j < CAP; ++j)
                        if (g_rows[c * CAP + j] == bb) { seen = true; break; }
                    if (!seen) {
                        float4 g0 = feat4[(size_t)bb * 64 + lane];
                        float4 g1 = feat4[(size_t)bb * 64 + lane + 32];
                        a0.x += s * g0.x; a0.y += s * g0.y;
                        a0.z += s * g0.z; a0.w += s * g0.w;
                        a1.x += s * g1.x; a1.y += s * g1.y;
                        a1.z += s * g1.z; a1.w += s * g1.w;
                    }
                }
            }
        }
    }

    float4* orow = reinterpret_cast<float4*>(out_centers) + (size_t)c * 64;
    orow[lane]      = a0;
    orow[lane + 32] = a1;
}

// ---------------------------------------------------------------------------
extern "C" void kernel_launch(void* const* d_in, const int* in_sizes, int n_in,
                              void* d_out, int out_size) {
    const float* feat    = (const float*)d_in[0];  // [4096, 256]
    const float* onehot  = (const float*)d_in[1];  // [4096, 10000]
    const float* centers = (const float*)d_in[2];  // [10000, 256]

    float* loss_out    = (float*)d_out;            // [4096]
    float* centers_out = (float*)d_out + BATCH;    // [10000, 256]

    // K1: 4096 rows, one warp each -> 512 blocks of 8 warps (exact)
    scan_loss_kernel<<<BATCH / 8, 256>>>(onehot, feat, centers, loss_out);

    // bulk copy centers -> out (DMA engine, full BW); overlapped ordering via
    // stream semantics: K2' (below) runs after it and overwrites touched rows
    cudaMemcpyAsync(centers_out, centers, (size_t)NCLS * DIM * sizeof(float),
                    cudaMemcpyDeviceToDevice);

    // K2': sparse update of touched classes only (one warp per class)
    sparse_update_kernel<<<NCLS * 32 / 256, 256>>>(centers, feat, centers_out);
}

// round 17
// speedup vs baseline: 1.0621x; 1.0621x over previous
#include <cuda_runtime.h>

#define BATCH 4096
#define NCLS  10000
#define DIM   256
#define ALPHA 0.5f
#define CAP   64   // per-class row-list capacity (overflow handled exactly)

// Scratch (allocation-free: __device__ globals).
// g_cnt starts zeroed (static init); K2 re-zeroes ONLY touched classes
// (untouched are already 0) -> no zero kernel.
__device__ int g_cnt[NCLS];         // per-class sample count
__device__ int g_label[BATCH];      // decoded label per row (overflow fallback)
__device__ int g_rows[NCLS * CAP];  // per-class row index list (8B aligned rows)

// ---------------------------------------------------------------------------
// K1: ONE WARP PER ROW, depth-1 software pipeline (measured-best K1 floor,
// ~21us). 4096 warps = 512 blocks of 8 warps. Each iteration covers 2 KB
// (4 float4/lane); next iteration's loads issue before testing the current
// buffer (ballot early-exit, warp-internal). Zero barriers, zero smem.
// ---------------------------------------------------------------------------
__global__ __launch_bounds__(256, 4)
void scan_loss_kernel(const float* __restrict__ onehot,
                      const float* __restrict__ feat,
                      const float* __restrict__ centers,
                      float* __restrict__ loss_out) {
    const int lane = threadIdx.x & 31;
    const int b    = blockIdx.x * 8 + (threadIdx.x >> 5);  // row for this warp

    const float4* row = reinterpret_cast<const float4*>(onehot + (size_t)b * NCLS);
    const int NV4 = NCLS / 4;            // 2500 float4
    const int PER_IT = 128;              // float4 per iteration (32 lanes x 4)
    const int NIT = (NV4 + PER_IT - 1) / PER_IT;  // 20

    float4 buf[4];
    #pragma unroll
    for (int k = 0; k < 4; ++k) {
        int i = lane + 32 * k;
        buf[k] = (i < NV4) ? row[i] : make_float4(0.f, 0.f, 0.f, 0.f);
    }

    int label = -1;
    #pragma unroll 1
    for (int it = 0; it < NIT; ++it) {
        // issue next iteration's loads BEFORE testing the current buffer
        float4 nxt[4];
        if (it + 1 < NIT) {
            #pragma unroll
            for (int k = 0; k < 4; ++k) {
                int i = (it + 1) * PER_IT + lane + 32 * k;
                nxt[k] = (i < NV4) ? row[i] : make_float4(0.f, 0.f, 0.f, 0.f);
            }
        }
        int found = -1;
        const int base = it * PER_IT;
        #pragma unroll
        for (int k = 0; k < 4; ++k) {
            int i = base + lane + 32 * k;
            if (buf[k].x != 0.f)      found = 4 * i + 0;
            else if (buf[k].y != 0.f) found = 4 * i + 1;
            else if (buf[k].z != 0.f) found = 4 * i + 2;
            else if (buf[k].w != 0.f) found = 4 * i + 3;
        }
        unsigned m = __ballot_sync(0xFFFFFFFFu, found >= 0);
        if (m) {
            const int src = __ffs(m) - 1;          // exactly one lane finds it
            if (lane == src) {
                g_label[b] = found;
                int slot = atomicAdd(&g_cnt[found], 1);
                if (slot < CAP) g_rows[found * CAP + slot] = b;
            }
            label = __shfl_sync(0xFFFFFFFFu, found, src);
            break;
        }
        #pragma unroll
        for (int k = 0; k < 4; ++k) buf[k] = nxt[k];
    }

    // loss vs OLD centers: lane owns dims [lane*8, lane*8+8)
    const float4* frow = reinterpret_cast<const float4*>(feat + (size_t)b * DIM);
    const float4* crow = reinterpret_cast<const float4*>(centers + (size_t)label * DIM);
    float4 fA = frow[lane * 2], fB = frow[lane * 2 + 1];
    float4 cA = crow[lane * 2], cB = crow[lane * 2 + 1];
    float dx, sq;
    dx = fA.x - cA.x; sq  = dx * dx;
    dx = fA.y - cA.y; sq += dx * dx;
    dx = fA.z - cA.z; sq += dx * dx;
    dx = fA.w - cA.w; sq += dx * dx;
    dx = fB.x - cB.x; sq += dx * dx;
    dx = fB.y - cB.y; sq += dx * dx;
    dx = fB.z - cB.z; sq += dx * dx;
    dx = fB.w - cB.w; sq += dx * dx;
    #pragma unroll
    for (int off = 16; off > 0; off >>= 1)
        sq += __shfl_down_sync(0xFFFFFFFFu, sq, off);
    if (lane == 0) loss_out[b] = sq;
}

// ---------------------------------------------------------------------------
// K2: one WARP per TWO adjacent classes. 5000 warps = 625 blocks of 256 =
// SINGLE WAVE (no wave-2 latency tail). Both counters arrive in one aligned
// int2 broadcast LDG; both centers rows + up to 8 feat gathers are
// independent (MLP up to 12). Both-zero fast path (43% of warps): pure
// 2-row copy, no counter store. Otherwise lane 0 cleans both counters with
// one int2 store AFTER the warp-wide load (warp program order, race-free,
// no barriers).
// ---------------------------------------------------------------------------
__global__ __launch_bounds__(256)
void scale_gather_kernel(const float* __restrict__ centers,
                         const float* __restrict__ feat,
                         float* __restrict__ out_centers) {
    const int w    = (blockIdx.x * blockDim.x + threadIdx.x) >> 5;  // warp id; grid exact
    const int lane = threadIdx.x & 31;
    const int c0   = w << 1;                  // even class; c1 = c0+1

    // level 0: both counters (one int2 broadcast) + both centers rows
    const int2 nn = *reinterpret_cast<const int2*>(&g_cnt[c0]);
    const float4* cr0 = reinterpret_cast<const float4*>(centers) + (size_t)c0 * 64;
    const float4* cr1 = cr0 + 64;
    float4 a00 = cr0[lane], a01 = cr0[lane + 32];
    float4 a10 = cr1[lane], a11 = cr1[lane + 32];
    float4* or0 = reinterpret_cast<float4*>(out_centers) + (size_t)c0 * 64;
    float4* or1 = or0 + 64;

    if ((nn.x | nn.y) == 0) {   // 43% of warps: both classes untouched
        or0[lane] = a00; or0[lane + 32] = a01;
        or1[lane] = a10; or1[lane + 32] = a11;
        return;
    }

    // clean both counters (8B store, after the warp-wide load: race-free)
    if (lane == 0) *reinterpret_cast<int2*>(&g_cnt[c0]) = make_int2(0, 0);

    const float4* feat4 = reinterpret_cast<const float4*>(feat);

    // ---- class c0 ----
    if (nn.x > 0) {
        const int n = nn.x;
        const int2 r01 = *reinterpret_cast<const int2*>(&g_rows[c0 * CAP]);
        const float s = __fdividef(ALPHA, (float)n + 1.0f);
        const float k = 1.0f - (float)n * s;
        a00.x *= k; a00.y *= k; a00.z *= k; a00.w *= k;
        a01.x *= k; a01.y *= k; a01.z *= k; a01.w *= k;
        float4 f0 = feat4[(size_t)r01.x * 64 + lane];
        float4 f1 = feat4[(size_t)r01.x * 64 + lane + 32];
        float4 g0 = make_float4(0.f, 0.f, 0.f, 0.f);
        float4 g1 = make_float4(0.f, 0.f, 0.f, 0.f);
        if (n >= 2) {
            g0 = feat4[(size_t)r01.y * 64 + lane];
            g1 = feat4[(size_t)r01.y * 64 + lane + 32];
        }
        a00.x += s * (f0.x + g0.x); a00.y += s * (f0.y + g0.y);
        a00.z += s * (f0.z + g0.z); a00.w += s * (f0.w + g0.w);
        a01.x += s * (f1.x + g1.x); a01.y += s * (f1.y + g1.y);
        a01.z += s * (f1.z + g1.z); a01.w += s * (f1.w + g1.w);
        if (n > 2) {
            const int m = (n <= CAP) ? n : CAP;
            #pragma unroll 1
            for (int j = 2; j < m; ++j) {
                int bj = g_rows[c0 * CAP + j];
                float4 h0 = feat4[(size_t)bj * 64 + lane];
                float4 h1 = feat4[(size_t)bj * 64 + lane + 32];
                a00.x += s * h0.x; a00.y += s * h0.y; a00.z += s * h0.z; a00.w += s * h0.w;
                a01.x += s * h1.x; a01.y += s * h1.y; a01.z += s * h1.z; a01.w += s * h1.w;
            }
            if (n > CAP) {  // exhaustive fallback (statistically unreachable; exact)
                #pragma unroll 1
                for (int bb = 0; bb < BATCH; ++bb) {
                    if (g_label[bb] == c0) {
                        bool seen = false;
                        for (int j = 0; j < CAP; ++j)
                            if (g_rows[c0 * CAP + j] == bb) { seen = true; break; }
                        if (!seen) {
                            float4 h0 = feat4[(size_t)bb * 64 + lane];
                            float4 h1 = feat4[(size_t)bb * 64 + lane + 32];
                            a00.x += s * h0.x; a00.y += s * h0.y;
                            a00.z += s * h0.z; a00.w += s * h0.w;
                            a01.x += s * h1.x; a01.y += s * h1.y;
                            a01.z += s * h1.z; a01.w += s * h1.w;
                        }
                    }
                }
            }
        }
    }

    // ---- class c1 ----
    if (nn.y > 0) {
        const int c1 = c0 + 1;
        const int n = nn.y;
        const int2 r01 = *reinterpret_cast<const int2*>(&g_rows[c1 * CAP]);
        const float s = __fdividef(ALPHA, (float)n + 1.0f);
        const float k = 1.0f - (float)n * s;
        a10.x *= k; a10.y *= k; a10.z *= k; a10.w *= k;
        a11.x *= k; a11.y *= k; a11.z *= k; a11.w *= k;
        float4 f0 = feat4[(size_t)r01.x * 64 + lane];
        float4 f1 = feat4[(size_t)r01.x * 64 + lane + 32];
        float4 g0 = make_float4(0.f, 0.f, 0.f, 0.f);
        float4 g1 = make_float4(0.f, 0.f, 0.f, 0.f);
        if (n >= 2) {
            g0 = feat4[(size_t)r01.y * 64 + lane];
            g1 = feat4[(size_t)r01.y * 64 + lane + 32];
        }
        a10.x += s * (f0.x + g0.x); a10.y += s * (f0.y + g0.y);
        a10.z += s * (f0.z + g0.z); a10.w += s * (f0.w + g0.w);
        a11.x += s * (f1.x + g1.x); a11.y += s * (f1.y + g1.y);
        a11.z += s * (f1.z + g1.z); a11.w += s * (f1.w + g1.w);
        if (n > 2) {
            const int m = (n <= CAP) ? n : CAP;
            #pragma unroll 1
            for (int j = 2; j < m; ++j) {
                int bj = g_rows[c1 * CAP + j];
                float4 h0 = feat4[(size_t)bj * 64 + lane];
                float4 h1 = feat4[(size_t)bj * 64 + lane + 32];
                a10.x += s * h0.x; a10.y += s * h0.y; a10.z += s * h0.z; a10.w += s * h0.w;
                a11.x += s * h1.x; a11.y += s * h1.y; a11.z += s * h1.z; a11.w += s * h1.w;
            }
            if (n > CAP) {  // exhaustive fallback (statistically unreachable; exact)
                #pragma unroll 1
                for (int bb = 0; bb < BATCH; ++bb) {
                    if (g_label[bb] == c1) {
                        bool seen = false;
                        for (int j = 0; j < CAP; ++j)
                            if (g_rows[c1 * CAP + j] == bb) { seen = true; break; }
                        if (!seen) {
                            float4 h0 = feat4[(size_t)bb * 64 + lane];
                            float4 h1 = feat4[(size_t)bb * 64 + lane + 32];
                            a10.x += s * h0.x; a10.y += s * h0.y;
                            a10.z += s * h0.z; a10.w += s * h0.w;
                            a11.x += s * h1.x; a11.y += s * h1.y;
                            a11.z += s * h1.z; a11.w += s * h1.w;
                        }
                    }
                }
            }
        }
    }

    or0[lane] = a00; or0[lane + 32] = a01;
    or1[lane] = a10; or1[lane + 32] = a11;
}

// ---------------------------------------------------------------------------
extern "C" void kernel_launch(void* const* d_in, const int* in_sizes, int n_in,
                              void* d_out, int out_size) {
    const float* feat    = (const float*)d_in[0];  // [4096, 256]
    const float* onehot  = (const float*)d_in[1];  // [4096, 10000]
    const float* centers = (const float*)d_in[2];  // [10000, 256]

    float* loss_out    = (float*)d_out;            // [4096]
    float* centers_out = (float*)d_out + BATCH;    // [10000, 256]

    // K1: 4096 rows, one warp each -> 512 blocks of 8 warps (exact)
    scan_loss_kernel<<<BATCH / 8, 256>>>(onehot, feat, centers, loss_out);
    // K2: 5000 warps (2 classes each) -> 625 blocks of 256 threads (exact)
    scale_gather_kernel<<<NCLS / 2 * 32 / 256, 256>>>(centers, feat, centers_out);
}